// round 10
// baseline (speedup 1.0000x reference)
#include <cuda_runtime.h>
#include <math.h>

#define NB 64
#define NT 512
#define NC 768
#define NH 192
#define ROT 32
#define M_TOT (NB*NT)

// Scratch for projected q, k, v (device globals: no allocation at launch time)
__device__ float g_q[M_TOT * NH];
__device__ float g_k[M_TOT * NH];
__device__ float g_v[M_TOT * NH];

// ============================================================================
// helpers
// ============================================================================
__device__ __forceinline__ float f2tf32(float x) {
    unsigned u;
    asm("cvt.rna.tf32.f32 %0, %1;" : "=r"(u) : "f"(x));
    return __uint_as_float(u);
}
__device__ __forceinline__ float4 f2tf32_4(float4 v) {
    return make_float4(f2tf32(v.x), f2tf32(v.y), f2tf32(v.z), f2tf32(v.w));
}
__device__ __forceinline__ float fast_ex2(float x) {
    float y;
    asm("ex2.approx.ftz.f32 %0, %1;" : "=f"(y) : "f"(x));
    return y;
}
#define L2E 1.4426950408889634f

#define LDSM4(r0, r1, r2, r3, addr) \
    asm volatile("ldmatrix.sync.aligned.m8n8.x4.shared.b16 {%0,%1,%2,%3}, [%4];" \
                 : "=r"(r0), "=r"(r1), "=r"(r2), "=r"(r3) : "r"(addr))

#define MMA_TF32(c0, c1, c2, c3, a0, a1, a2, a3, b0, b1) \
    asm volatile( \
        "mma.sync.aligned.m16n8k8.row.col.f32.tf32.tf32.f32 " \
        "{%0,%1,%2,%3}, {%4,%5,%6,%7}, {%8,%9}, {%0,%1,%2,%3};\n" \
        : "+f"(c0), "+f"(c1), "+f"(c2), "+f"(c3) \
        : "r"(a0), "r"(a1), "r"(a2), "r"(a3), "r"(b0), "r"(b1))

// ============================================================================
// QKV projection: out = X(32768,768) @ W(768,192), RoPE fused for q,k.
// tf32 mma.sync.m16n8k8, ldmatrix fragment loads, full-N tile.
// Block tile 128x192, BK=16, 512 threads (16 warps as 4Mx4N, warp 32x48).
// B stored n-major [n][k] in smem so the B fragment is a non-trans LDSM.
// ============================================================================
#define GBM 128
#define GBK 16
#define LDA 20    // As row stride: LDSM phase banks 20r mod 32 unique
#define LDBN 20   // Bsn row stride: same property
#define ASZ (GBM * LDA)          // 2560 floats
#define BSZ (NH * LDBN)          // 3840 floats
#define A_BUF_BYTES (ASZ * 4)    // 10240
#define B_BUF_BYTES (BSZ * 4)    // 15360
#define QKV_SMEM_BYTES ((2 * ASZ + 2 * BSZ) * 4)   // 51200

__global__ __launch_bounds__(512)
void qkv_mma(const float* __restrict__ X,
             const float* __restrict__ Wq,
             const float* __restrict__ Wk,
             const float* __restrict__ Wv)
{
    extern __shared__ float qsm[];
    float* Asm = qsm;               // [2][ASZ]   m-major [m][k]
    float* Bsm = qsm + 2 * ASZ;     // [2][BSZ]   n-major [n][k]

    const int which = blockIdx.y;
    const float* W  = (which == 0) ? Wq : (which == 1) ? Wk : Wv;
    float* outp     = (which == 0) ? g_q : (which == 1) ? g_k : g_v;
    const bool rope = (which < 2);

    const int m0 = blockIdx.x * GBM;

    const int tid  = threadIdx.x;
    const int lane = tid & 31;
    const int wid  = tid >> 5;
    const int wm   = (wid & 3) * 32;    // warp M offset
    const int wn   = (wid >> 2) * 48;   // warp N offset
    const int g    = lane >> 2;
    const int t    = lane & 3;

    // ---- global loader indices ----
    const int am = tid >> 2;            // 0..127
    const int ak = (tid & 3) * 4;       // 0,4,8,12
    const float* Ag = X + (size_t)(m0 + am) * NC + ak;

    // B: 16x192 tile, 512 threads x 3 float2
    int brow[3], bcol[3];
    #pragma unroll
    for (int j = 0; j < 3; j++) {
        int e = tid + j * 512;          // 0..1535
        brow[j] = e / 96;               // 0..15 (k)
        bcol[j] = (e - brow[j] * 96) * 2;  // 0..190 even (n)
    }

    // ---- LDSM per-lane base addresses (byte offsets into smem) ----
    const unsigned sA = (unsigned)__cvta_generic_to_shared(Asm);
    const unsigned sB = (unsigned)__cvta_generic_to_shared(Bsm);
    unsigned a_addr[2];
    #pragma unroll
    for (int mi = 0; mi < 2; mi++) {
        int rowA = wm + mi * 16 + (lane & 15);
        int colA = (lane >> 4) * 4;
        a_addr[mi] = sA + (unsigned)(rowA * LDA + colA) * 4u;
    }
    unsigned b_addr[3];
    #pragma unroll
    for (int n2 = 0; n2 < 3; n2++) {
        int rowB = wn + n2 * 16 + (lane & 7) + ((lane >> 4) << 3);
        int colB = ((lane >> 3) & 1) * 4;
        b_addr[n2] = sB + (unsigned)(rowB * LDBN + colB) * 4u;
    }

    float c[2][6][4];
    #pragma unroll
    for (int mi = 0; mi < 2; mi++)
        #pragma unroll
        for (int ni = 0; ni < 6; ni++)
            #pragma unroll
            for (int r = 0; r < 4; r++) c[mi][ni][r] = 0.f;

    const int K_TILES = NC / GBK;   // 48

    float4 ra;
    float2 rb[3];

    // ---- prologue: tile 0 ----
    ra = *(const float4*)(Ag);
    #pragma unroll
    for (int j = 0; j < 3; j++)
        rb[j] = *(const float2*)(W + (size_t)brow[j] * NH + bcol[j]);
    *(float4*)&Asm[am * LDA + ak] = f2tf32_4(ra);
    #pragma unroll
    for (int j = 0; j < 3; j++) {
        Bsm[(bcol[j] + 0) * LDBN + brow[j]] = f2tf32(rb[j].x);
        Bsm[(bcol[j] + 1) * LDBN + brow[j]] = f2tf32(rb[j].y);
    }
    __syncthreads();

    for (int kt = 0; kt < K_TILES; kt++) {
        const int cur = kt & 1;
        const bool more = (kt + 1 < K_TILES);
        if (more) {
            int k0 = (kt + 1) * GBK;
            ra = *(const float4*)(Ag + k0);
            #pragma unroll
            for (int j = 0; j < 3; j++)
                rb[j] = *(const float2*)(W + (size_t)(k0 + brow[j]) * NH + bcol[j]);
        }

        const unsigned aoff = cur ? A_BUF_BYTES : 0u;
        const unsigned boff = cur ? B_BUF_BYTES : 0u;

        #pragma unroll
        for (int ks = 0; ks < GBK; ks += 8) {
            unsigned af[2][4];
            unsigned bf[6][2];
            #pragma unroll
            for (int mi = 0; mi < 2; mi++)
                LDSM4(af[mi][0], af[mi][1], af[mi][2], af[mi][3],
                      a_addr[mi] + aoff + ks * 4u);
            #pragma unroll
            for (int n2 = 0; n2 < 3; n2++)
                LDSM4(bf[2 * n2][0], bf[2 * n2][1], bf[2 * n2 + 1][0], bf[2 * n2 + 1][1],
                      b_addr[n2] + boff + ks * 4u);
            #pragma unroll
            for (int mi = 0; mi < 2; mi++)
                #pragma unroll
                for (int ni = 0; ni < 6; ni++)
                    MMA_TF32(c[mi][ni][0], c[mi][ni][1], c[mi][ni][2], c[mi][ni][3],
                             af[mi][0], af[mi][1], af[mi][2], af[mi][3],
                             bf[ni][0], bf[ni][1]);
        }

        if (more) {
            const unsigned nxtA = cur ? 0u : ASZ;
            const unsigned nxtB = cur ? 0u : BSZ;
            *(float4*)&Asm[nxtA + am * LDA + ak] = f2tf32_4(ra);
            #pragma unroll
            for (int j = 0; j < 3; j++) {
                Bsm[nxtB + (bcol[j] + 0) * LDBN + brow[j]] = f2tf32(rb[j].x);
                Bsm[nxtB + (bcol[j] + 1) * LDBN + brow[j]] = f2tf32(rb[j].y);
            }
            __syncthreads();
        }
    }

    // ---- epilogue: RoPE on cols < 32 (q,k only), store float2 pairs ----
    const float LOG2_THETA = 13.287712379549449f;

    #pragma unroll
    for (int mi = 0; mi < 2; mi++) {
        #pragma unroll
        for (int ni = 0; ni < 6; ni++) {
            int col = wn + ni * 8 + t * 2;   // even column, global (n0 == 0)
            #pragma unroll
            for (int half = 0; half < 2; half++) {
                int row = m0 + wm + mi * 16 + g + half * 8;
                float x1 = c[mi][ni][half * 2 + 0];
                float x2 = c[mi][ni][half * 2 + 1];
                if (rope && col < ROT) {
                    int jh = col >> 1;
                    int tpos = row & (NT - 1);
                    float inv = exp2f(-(float)(2 * jh) * (1.0f / 32.0f) * LOG2_THETA);
                    float ang = (float)tpos * inv;
                    float sn, cs;
                    sincosf(ang, &sn, &cs);
                    float r1 = x1 * cs - x2 * sn;
                    float r2 = x2 * cs + x1 * sn;
                    x1 = r1; x2 = r2;
                }
                *(float2*)&outp[(size_t)row * NH + col] = make_float2(x1, x2);
            }
        }
    }
}

// ============================================================================
// Tensor-core flash attention (tf32 mma for S=QK^T and O=PV).
// Block = (batch b, query tile of 64 rows). 256 threads = 8 warps.
// ============================================================================
#define BQ  64
#define BKT 64
#define LDQ 196  // Q/K smem row stride (floats): frag bank = 4*row+t, unique
#define LDV 200  // V smem row stride: frag bank = 8*t+g, unique
#define LDS 68   // S smem row stride: frag bank = 4*row+t, unique

#define ATTN_SMEM_FLOATS (BQ*LDQ + BKT*LDQ + BKT*LDV + BQ*LDS + 3*BQ)

__global__ __launch_bounds__(256)
void attn_mma(float* __restrict__ out)
{
    extern __shared__ float sm[];
    float* Qs  = sm;                  // [64][LDQ]
    float* Ks  = Qs  + BQ * LDQ;      // [64][LDQ]  natural row-major
    float* Vs  = Ks  + BKT * LDQ;     // [64][LDV]  natural row-major
    float* Ss  = Vs  + BKT * LDV;     // [64][LDS]
    float* m_s = Ss  + BQ * LDS;      // [64]
    float* l_s = m_s + BQ;            // [64]
    float* c_s = l_s + BQ;            // [64]

    const int b   = blockIdx.y;
    const int qt  = gridDim.x - 1 - blockIdx.x;   // heavy tiles first
    const int q0  = qt * BQ;
    const int tid = threadIdx.x;
    const int lane = tid & 31;
    const int wid  = tid >> 5;
    const int g    = lane >> 2;       // 0..7
    const int t    = lane & 3;        // 0..3
    const int wm   = (wid & 3) * 16;  // warp M offset (rows)
    const int wns  = (wid >> 2) * 32; // warp N offset for S
    const int wnv  = (wid >> 2) * 96; // warp N offset for PV / O

    // ---- load Q tile (tf32-rounded) ----
    {
        const float4* src = (const float4*)(g_q + ((size_t)b * NT + q0) * NH);
        #pragma unroll
        for (int i = 0; i < 12; i++) {
            int e = tid + i * 256;          // 0..3071 float4s
            int row = e / 48, c4 = e - row * 48;
            float4 v = src[e];
            *(float4*)&Qs[row * LDQ + c4 * 4] = f2tf32_4(v);
        }
    }
    if (tid < BQ) { m_s[tid] = -INFINITY; l_s[tid] = 0.f; }

    float o[12][4];
    #pragma unroll
    for (int ni = 0; ni < 12; ni++)
        #pragma unroll
        for (int r = 0; r < 4; r++) o[ni][r] = 0.f;

    const float scale = 1.0f / sqrtf((float)NH);

    for (int kt = 0; kt <= qt; kt++) {
        __syncthreads();   // prev PV done before K/V/S overwrite

        // ---- load K, V tiles (tf32-rounded) ----
        {
            const float4* ksrc = (const float4*)(g_k + ((size_t)b * NT + kt * BKT) * NH);
            const float4* vsrc = (const float4*)(g_v + ((size_t)b * NT + kt * BKT) * NH);
            #pragma unroll
            for (int i = 0; i < 12; i++) {
                int e = tid + i * 256;
                int row = e / 48, c4 = e - row * 48;
                float4 kv = ksrc[e];
                *(float4*)&Ks[row * LDQ + c4 * 4] = f2tf32_4(kv);
                float4 vv = vsrc[e];
                *(float4*)&Vs[row * LDV + c4 * 4] = f2tf32_4(vv);
            }
        }
        __syncthreads();

        // ---- S = Q K^T via mma (each warp: 16 rows x 32 cols) ----
        float s[4][4];
        #pragma unroll
        for (int ni = 0; ni < 4; ni++)
            #pragma unroll
            for (int r = 0; r < 4; r++) s[ni][r] = 0.f;

        #pragma unroll 4
        for (int ks = 0; ks < NH; ks += 8) {
            unsigned af[4];
            int r0 = (wm + g) * LDQ + ks + t;
            int r1 = (wm + 8 + g) * LDQ + ks + t;
            af[0] = __float_as_uint(Qs[r0]);
            af[1] = __float_as_uint(Qs[r1]);
            af[2] = __float_as_uint(Qs[r0 + 4]);
            af[3] = __float_as_uint(Qs[r1 + 4]);
            #pragma unroll
            for (int ni = 0; ni < 4; ni++) {
                int col = wns + ni * 8 + g;
                unsigned b0 = __float_as_uint(Ks[col * LDQ + ks + t]);
                unsigned b1 = __float_as_uint(Ks[col * LDQ + ks + t + 4]);
                MMA_TF32(s[ni][0], s[ni][1], s[ni][2], s[ni][3],
                         af[0], af[1], af[2], af[3], b0, b1);
            }
        }

        // ---- scale + causal mask, write S to smem ----
        const bool diag = (kt == qt);
        #pragma unroll
        for (int ni = 0; ni < 4; ni++) {
            #pragma unroll
            for (int half = 0; half < 2; half++) {
                int row = wm + half * 8 + g;
                #pragma unroll
                for (int j = 0; j < 2; j++) {
                    int col = wns + ni * 8 + t * 2 + j;
                    float v = s[ni][half * 2 + j] * scale;
                    if (diag && col > row) v = -INFINITY;
                    Ss[row * LDS + col] = v;
                }
            }
        }
        __syncthreads();

        // ---- online softmax: 4 threads per row, 16 cols each ----
        {
            int r   = tid >> 2;
            int sub = tid & 3;
            float* rp = Ss + r * LDS + sub * 16;

            float p[16];
            *(float4*)(p + 0)  = *(float4*)(rp + 0);
            *(float4*)(p + 4)  = *(float4*)(rp + 4);
            *(float4*)(p + 8)  = *(float4*)(rp + 8);
            *(float4*)(p + 12) = *(float4*)(rp + 12);

            float tmax = p[0];
            #pragma unroll
            for (int i = 1; i < 16; i++) tmax = fmaxf(tmax, p[i]);
            tmax = fmaxf(tmax, __shfl_xor_sync(0xffffffffu, tmax, 1));
            tmax = fmaxf(tmax, __shfl_xor_sync(0xffffffffu, tmax, 2));

            float mo   = m_s[r];
            float rmax = fmaxf(mo, tmax);
            float corr = fast_ex2((mo - rmax) * L2E);

            float sum = 0.f;
            #pragma unroll
            for (int i = 0; i < 16; i++) {
                float e = fast_ex2((p[i] - rmax) * L2E);
                sum += e;
                p[i] = f2tf32(e);
            }
            *(float4*)(rp + 0)  = *(float4*)(p + 0);
            *(float4*)(rp + 4)  = *(float4*)(p + 4);
            *(float4*)(rp + 8)  = *(float4*)(p + 8);
            *(float4*)(rp + 12) = *(float4*)(p + 12);

            sum += __shfl_xor_sync(0xffffffffu, sum, 1);
            sum += __shfl_xor_sync(0xffffffffu, sum, 2);
            if (sub == 0) {
                l_s[r] = l_s[r] * corr + sum;
                m_s[r] = rmax;
                c_s[r] = corr;
            }
        }
        __syncthreads();

        // ---- O = O*corr + P V via mma (each warp: 16 rows x 96 cols) ----
        {
            float corr0 = c_s[wm + g];
            float corr1 = c_s[wm + 8 + g];
            #pragma unroll
            for (int ni = 0; ni < 12; ni++) {
                o[ni][0] *= corr0; o[ni][1] *= corr0;
                o[ni][2] *= corr1; o[ni][3] *= corr1;
            }
        }
        #pragma unroll
        for (int kk = 0; kk < BKT; kk += 8) {
            unsigned af[4];
            int r0 = (wm + g) * LDS + kk + t;
            int r1 = (wm + 8 + g) * LDS + kk + t;
            af[0] = __float_as_uint(Ss[r0]);
            af[1] = __float_as_uint(Ss[r1]);
            af[2] = __float_as_uint(Ss[r0 + 4]);
            af[3] = __float_as_uint(Ss[r1 + 4]);
            #pragma unroll
            for (int ni = 0; ni < 12; ni++) {
                int col = wnv + ni * 8 + g;
                unsigned b0 = __float_as_uint(Vs[(kk + t) * LDV + col]);
                unsigned b1 = __float_as_uint(Vs[(kk + t + 4) * LDV + col]);
                MMA_TF32(o[ni][0], o[ni][1], o[ni][2], o[ni][3],
                         af[0], af[1], af[2], af[3], b0, b1);
            }
        }
    }

    // ---- finalize: O / l, store ----
    __syncthreads();
    {
        float inv0 = 1.0f / l_s[wm + g];
        float inv1 = 1.0f / l_s[wm + 8 + g];
        float* ob = out + ((size_t)b * NT + q0) * NH;
        #pragma unroll
        for (int ni = 0; ni < 12; ni++) {
            int col = wnv + ni * 8 + t * 2;
            int row0 = wm + g;
            int row1 = wm + 8 + g;
            *(float2*)&ob[(size_t)row0 * NH + col] =
                make_float2(o[ni][0] * inv0, o[ni][1] * inv0);
            *(float2*)&ob[(size_t)row1 * NH + col] =
                make_float2(o[ni][2] * inv1, o[ni][3] * inv1);
        }
    }
}

// ============================================================================
// Launch
// ============================================================================
extern "C" void kernel_launch(void* const* d_in, const int* in_sizes, int n_in,
                              void* d_out, int out_size)
{
    const float* x  = (const float*)d_in[0];
    const float* Wq = (const float*)d_in[1];
    const float* Wk = (const float*)d_in[2];
    const float* Wv = (const float*)d_in[3];
    float* out = (float*)d_out;

    (void)in_sizes; (void)n_in; (void)out_size;

    // QKV projections (full-N tile, ldmatrix + tf32 mma)
    cudaFuncSetAttribute(qkv_mma, cudaFuncAttributeMaxDynamicSharedMemorySize,
                         QKV_SMEM_BYTES);
    dim3 ggrd(M_TOT / GBM, 3);      // (256, 3)
    qkv_mma<<<ggrd, 512, QKV_SMEM_BYTES>>>(x, Wq, Wk, Wv);

    // Attention
    size_t smem = ATTN_SMEM_FLOATS * sizeof(float);
    cudaFuncSetAttribute(attn_mma, cudaFuncAttributeMaxDynamicSharedMemorySize, (int)smem);
    dim3 agrd(NT / BQ, NB);         // (8, 64)
    attn_mma<<<agrd, 256, smem>>>(out);
}

// round 11
// speedup vs baseline: 1.1833x; 1.1833x over previous
#include <cuda_runtime.h>
#include <math.h>

#define NB 64
#define NT 512
#define NC 768
#define NH 192
#define ROT 32
#define M_TOT (NB*NT)

// Scratch for projected q, k, v (device globals: no allocation at launch time)
__device__ float g_q[M_TOT * NH];
__device__ float g_k[M_TOT * NH];
__device__ float g_v[M_TOT * NH];

// ============================================================================
// helpers
// ============================================================================
__device__ __forceinline__ float f2tf32(float x) {
    unsigned u;
    asm("cvt.rna.tf32.f32 %0, %1;" : "=r"(u) : "f"(x));
    return __uint_as_float(u);
}
__device__ __forceinline__ float4 f2tf32_4(float4 v) {
    return make_float4(f2tf32(v.x), f2tf32(v.y), f2tf32(v.z), f2tf32(v.w));
}
__device__ __forceinline__ float fast_ex2(float x) {
    float y;
    asm("ex2.approx.ftz.f32 %0, %1;" : "=f"(y) : "f"(x));
    return y;
}
#define L2E 1.4426950408889634f

#define MMA_TF32(c0, c1, c2, c3, a0, a1, a2, a3, b0, b1) \
    asm volatile( \
        "mma.sync.aligned.m16n8k8.row.col.f32.tf32.tf32.f32 " \
        "{%0,%1,%2,%3}, {%4,%5,%6,%7}, {%8,%9}, {%0,%1,%2,%3};\n" \
        : "+f"(c0), "+f"(c1), "+f"(c2), "+f"(c3) \
        : "r"(a0), "r"(a1), "r"(a2), "r"(a3), "r"(b0), "r"(b1))

// ============================================================================
// QKV projection: out = X(32768,768) @ W(768,192), RoPE fused for q,k.
// tf32 mma.sync.m16n8k8. Block tile 64x192 (full N), BK=16, 256 threads
// (8 warps as 2Mx4N, warp tile 32x48). Double-buffered smem, 1 sync/tile.
// ============================================================================
#define GBM 64
#define GBK 16
#define LDA 20    // As row stride: frag banks (20*row + t) mod 32, unique per warp phase
#define LDB 200   // Bs row stride: frag banks (8t + g), unique (200 mod 32 = 8)
#define ASZ (GBM * LDA)    // 1280 floats
#define BSZ (GBK * LDB)    // 3200 floats

__global__ __launch_bounds__(256)
void qkv_mma(const float* __restrict__ X,
             const float* __restrict__ Wq,
             const float* __restrict__ Wk,
             const float* __restrict__ Wv)
{
    __shared__ float As[2][ASZ];   // [m][k] m-major
    __shared__ float Bs[2][BSZ];   // [k][n] k-major

    const int which = blockIdx.y;
    const float* W  = (which == 0) ? Wq : (which == 1) ? Wk : Wv;
    float* outp     = (which == 0) ? g_q : (which == 1) ? g_k : g_v;
    const bool rope = (which < 2);

    const int m0 = blockIdx.x * GBM;

    const int tid  = threadIdx.x;
    const int lane = tid & 31;
    const int wid  = tid >> 5;
    const int wm   = (wid & 1) * 32;    // warp M offset
    const int wn   = (wid >> 1) * 48;   // warp N offset
    const int g    = lane >> 2;
    const int t    = lane & 3;

    // ---- global loader indices ----
    // A: 64x16 tile = 256 float4, 1 per thread
    const int am = tid >> 2;            // 0..63
    const int ak = (tid & 3) * 4;       // 0,4,8,12
    const float* Ag = X + (size_t)(m0 + am) * NC + ak;

    // B: 16x192 tile = 768 float4, 3 per thread
    int brow[3], bcol[3];
    #pragma unroll
    for (int j = 0; j < 3; j++) {
        int e = tid + j * 256;          // 0..767
        brow[j] = e / 48;               // 0..15 (k)
        bcol[j] = (e - brow[j] * 48) * 4;  // 0..188 (n, multiple of 4)
    }

    float4 ra;
    float4 rb[3];

    float c[2][6][4];
    #pragma unroll
    for (int mi = 0; mi < 2; mi++)
        #pragma unroll
        for (int ni = 0; ni < 6; ni++)
            #pragma unroll
            for (int r = 0; r < 4; r++) c[mi][ni][r] = 0.f;

    const int K_TILES = NC / GBK;   // 48

    // ---- prologue: tile 0 ----
    ra = *(const float4*)(Ag);
    #pragma unroll
    for (int j = 0; j < 3; j++)
        rb[j] = *(const float4*)(W + (size_t)brow[j] * NH + bcol[j]);
    *(float4*)&As[0][am * LDA + ak] = f2tf32_4(ra);
    #pragma unroll
    for (int j = 0; j < 3; j++)
        *(float4*)&Bs[0][brow[j] * LDB + bcol[j]] = f2tf32_4(rb[j]);
    __syncthreads();

    for (int kt = 0; kt < K_TILES; kt++) {
        const int cur = kt & 1;
        const bool more = (kt + 1 < K_TILES);
        if (more) {
            int k0 = (kt + 1) * GBK;
            ra = *(const float4*)(Ag + k0);
            #pragma unroll
            for (int j = 0; j < 3; j++)
                rb[j] = *(const float4*)(W + (size_t)(k0 + brow[j]) * NH + bcol[j]);
        }

        const float* Ac = As[cur];
        const float* Bc = Bs[cur];
        #pragma unroll
        for (int ks = 0; ks < GBK; ks += 8) {
            unsigned af[2][4];
            unsigned bf[6][2];
            #pragma unroll
            for (int mi = 0; mi < 2; mi++) {
                int r0 = (wm + mi * 16 + g) * LDA + ks + t;
                int r1 = (wm + mi * 16 + 8 + g) * LDA + ks + t;
                af[mi][0] = __float_as_uint(Ac[r0]);
                af[mi][1] = __float_as_uint(Ac[r1]);
                af[mi][2] = __float_as_uint(Ac[r0 + 4]);
                af[mi][3] = __float_as_uint(Ac[r1 + 4]);
            }
            #pragma unroll
            for (int ni = 0; ni < 6; ni++) {
                int col = wn + ni * 8 + g;
                bf[ni][0] = __float_as_uint(Bc[(ks + t) * LDB + col]);
                bf[ni][1] = __float_as_uint(Bc[(ks + t + 4) * LDB + col]);
            }
            #pragma unroll
            for (int mi = 0; mi < 2; mi++)
                #pragma unroll
                for (int ni = 0; ni < 6; ni++)
                    MMA_TF32(c[mi][ni][0], c[mi][ni][1], c[mi][ni][2], c[mi][ni][3],
                             af[mi][0], af[mi][1], af[mi][2], af[mi][3],
                             bf[ni][0], bf[ni][1]);
        }

        if (more) {
            const int nxt = cur ^ 1;
            *(float4*)&As[nxt][am * LDA + ak] = f2tf32_4(ra);
            #pragma unroll
            for (int j = 0; j < 3; j++)
                *(float4*)&Bs[nxt][brow[j] * LDB + bcol[j]] = f2tf32_4(rb[j]);
            __syncthreads();
        }
    }

    // ---- epilogue: RoPE on cols < 32 (q,k only), store float2 pairs ----
    const float LOG2_THETA = 13.287712379549449f;

    #pragma unroll
    for (int mi = 0; mi < 2; mi++) {
        #pragma unroll
        for (int ni = 0; ni < 6; ni++) {
            int col = wn + ni * 8 + t * 2;   // even column (global, full N tile)
            #pragma unroll
            for (int half = 0; half < 2; half++) {
                int row = m0 + wm + mi * 16 + g + half * 8;
                float x1 = c[mi][ni][half * 2 + 0];
                float x2 = c[mi][ni][half * 2 + 1];
                if (rope && col < ROT) {
                    int jh = col >> 1;
                    int tpos = row & (NT - 1);
                    float inv = exp2f(-(float)(2 * jh) * (1.0f / 32.0f) * LOG2_THETA);
                    float ang = (float)tpos * inv;
                    float sn, cs;
                    sincosf(ang, &sn, &cs);
                    float r1 = x1 * cs - x2 * sn;
                    float r2 = x2 * cs + x1 * sn;
                    x1 = r1; x2 = r2;
                }
                *(float2*)&outp[(size_t)row * NH + col] = make_float2(x1, x2);
            }
        }
    }
}

// ============================================================================
// Tensor-core flash attention (tf32 mma for S=QK^T and O=PV).
// Block = (batch b, query tile of 64 rows). 256 threads = 8 warps.
// ============================================================================
#define BQ  64
#define BKT 64
#define LDQ 196  // Q/K smem row stride (floats): frag bank = 4*row+t, unique
#define LDV 200  // V smem row stride: frag bank = 8*t+g, unique
#define LDS 68   // S smem row stride: frag bank = 4*row+t, unique

#define ATTN_SMEM_FLOATS (BQ*LDQ + BKT*LDQ + BKT*LDV + BQ*LDS + 3*BQ)

__global__ __launch_bounds__(256)
void attn_mma(float* __restrict__ out)
{
    extern __shared__ float sm[];
    float* Qs  = sm;                  // [64][LDQ]
    float* Ks  = Qs  + BQ * LDQ;      // [64][LDQ]  natural row-major
    float* Vs  = Ks  + BKT * LDQ;     // [64][LDV]  natural row-major
    float* Ss  = Vs  + BKT * LDV;     // [64][LDS]
    float* m_s = Ss  + BQ * LDS;      // [64]
    float* l_s = m_s + BQ;            // [64]
    float* c_s = l_s + BQ;            // [64]

    const int b   = blockIdx.y;
    const int qt  = gridDim.x - 1 - blockIdx.x;   // heavy tiles first
    const int q0  = qt * BQ;
    const int tid = threadIdx.x;
    const int lane = tid & 31;
    const int wid  = tid >> 5;
    const int g    = lane >> 2;       // 0..7
    const int t    = lane & 3;        // 0..3
    const int wm   = (wid & 3) * 16;  // warp M offset (rows)
    const int wns  = (wid >> 2) * 32; // warp N offset for S
    const int wnv  = (wid >> 2) * 96; // warp N offset for PV / O

    // ---- load Q tile (tf32-rounded) ----
    {
        const float4* src = (const float4*)(g_q + ((size_t)b * NT + q0) * NH);
        #pragma unroll
        for (int i = 0; i < 12; i++) {
            int e = tid + i * 256;          // 0..3071 float4s
            int row = e / 48, c4 = e - row * 48;
            float4 v = src[e];
            *(float4*)&Qs[row * LDQ + c4 * 4] = f2tf32_4(v);
        }
    }
    if (tid < BQ) { m_s[tid] = -INFINITY; l_s[tid] = 0.f; }

    float o[12][4];
    #pragma unroll
    for (int ni = 0; ni < 12; ni++)
        #pragma unroll
        for (int r = 0; r < 4; r++) o[ni][r] = 0.f;

    const float scale = 1.0f / sqrtf((float)NH);

    for (int kt = 0; kt <= qt; kt++) {
        __syncthreads();   // prev PV done before K/V/S overwrite

        // ---- load K, V tiles (tf32-rounded) ----
        {
            const float4* ksrc = (const float4*)(g_k + ((size_t)b * NT + kt * BKT) * NH);
            const float4* vsrc = (const float4*)(g_v + ((size_t)b * NT + kt * BKT) * NH);
            #pragma unroll
            for (int i = 0; i < 12; i++) {
                int e = tid + i * 256;
                int row = e / 48, c4 = e - row * 48;
                float4 kv = ksrc[e];
                *(float4*)&Ks[row * LDQ + c4 * 4] = f2tf32_4(kv);
                float4 vv = vsrc[e];
                *(float4*)&Vs[row * LDV + c4 * 4] = f2tf32_4(vv);
            }
        }
        __syncthreads();

        // ---- S = Q K^T via mma (each warp: 16 rows x 32 cols) ----
        float s[4][4];
        #pragma unroll
        for (int ni = 0; ni < 4; ni++)
            #pragma unroll
            for (int r = 0; r < 4; r++) s[ni][r] = 0.f;

        #pragma unroll 4
        for (int ks = 0; ks < NH; ks += 8) {
            unsigned af[4];
            int r0 = (wm + g) * LDQ + ks + t;
            int r1 = (wm + 8 + g) * LDQ + ks + t;
            af[0] = __float_as_uint(Qs[r0]);
            af[1] = __float_as_uint(Qs[r1]);
            af[2] = __float_as_uint(Qs[r0 + 4]);
            af[3] = __float_as_uint(Qs[r1 + 4]);
            #pragma unroll
            for (int ni = 0; ni < 4; ni++) {
                int col = wns + ni * 8 + g;
                unsigned b0 = __float_as_uint(Ks[col * LDQ + ks + t]);
                unsigned b1 = __float_as_uint(Ks[col * LDQ + ks + t + 4]);
                MMA_TF32(s[ni][0], s[ni][1], s[ni][2], s[ni][3],
                         af[0], af[1], af[2], af[3], b0, b1);
            }
        }

        // ---- scale + causal mask, write S to smem ----
        const bool diag = (kt == qt);
        #pragma unroll
        for (int ni = 0; ni < 4; ni++) {
            #pragma unroll
            for (int half = 0; half < 2; half++) {
                int row = wm + half * 8 + g;
                #pragma unroll
                for (int j = 0; j < 2; j++) {
                    int col = wns + ni * 8 + t * 2 + j;
                    float v = s[ni][half * 2 + j] * scale;
                    if (diag && col > row) v = -INFINITY;
                    Ss[row * LDS + col] = v;
                }
            }
        }
        __syncthreads();

        // ---- online softmax: 4 threads per row, 16 cols each ----
        {
            int r   = tid >> 2;
            int sub = tid & 3;
            float* rp = Ss + r * LDS + sub * 16;

            float p[16];
            *(float4*)(p + 0)  = *(float4*)(rp + 0);
            *(float4*)(p + 4)  = *(float4*)(rp + 4);
            *(float4*)(p + 8)  = *(float4*)(rp + 8);
            *(float4*)(p + 12) = *(float4*)(rp + 12);

            float tmax = p[0];
            #pragma unroll
            for (int i = 1; i < 16; i++) tmax = fmaxf(tmax, p[i]);
            tmax = fmaxf(tmax, __shfl_xor_sync(0xffffffffu, tmax, 1));
            tmax = fmaxf(tmax, __shfl_xor_sync(0xffffffffu, tmax, 2));

            float mo   = m_s[r];
            float rmax = fmaxf(mo, tmax);
            float corr = fast_ex2((mo - rmax) * L2E);

            float sum = 0.f;
            #pragma unroll
            for (int i = 0; i < 16; i++) {
                float e = fast_ex2((p[i] - rmax) * L2E);
                sum += e;
                p[i] = f2tf32(e);
            }
            *(float4*)(rp + 0)  = *(float4*)(p + 0);
            *(float4*)(rp + 4)  = *(float4*)(p + 4);
            *(float4*)(rp + 8)  = *(float4*)(p + 8);
            *(float4*)(rp + 12) = *(float4*)(p + 12);

            sum += __shfl_xor_sync(0xffffffffu, sum, 1);
            sum += __shfl_xor_sync(0xffffffffu, sum, 2);
            if (sub == 0) {
                l_s[r] = l_s[r] * corr + sum;
                m_s[r] = rmax;
                c_s[r] = corr;
            }
        }
        __syncthreads();

        // ---- O = O*corr + P V via mma (each warp: 16 rows x 96 cols) ----
        {
            float corr0 = c_s[wm + g];
            float corr1 = c_s[wm + 8 + g];
            #pragma unroll
            for (int ni = 0; ni < 12; ni++) {
                o[ni][0] *= corr0; o[ni][1] *= corr0;
                o[ni][2] *= corr1; o[ni][3] *= corr1;
            }
        }
        #pragma unroll
        for (int kk = 0; kk < BKT; kk += 8) {
            unsigned af[4];
            int r0 = (wm + g) * LDS + kk + t;
            int r1 = (wm + 8 + g) * LDS + kk + t;
            af[0] = __float_as_uint(Ss[r0]);
            af[1] = __float_as_uint(Ss[r1]);
            af[2] = __float_as_uint(Ss[r0 + 4]);
            af[3] = __float_as_uint(Ss[r1 + 4]);
            #pragma unroll
            for (int ni = 0; ni < 12; ni++) {
                int col = wnv + ni * 8 + g;
                unsigned b0 = __float_as_uint(Vs[(kk + t) * LDV + col]);
                unsigned b1 = __float_as_uint(Vs[(kk + t + 4) * LDV + col]);
                MMA_TF32(o[ni][0], o[ni][1], o[ni][2], o[ni][3],
                         af[0], af[1], af[2], af[3], b0, b1);
            }
        }
    }

    // ---- finalize: O / l, store ----
    __syncthreads();
    {
        float inv0 = 1.0f / l_s[wm + g];
        float inv1 = 1.0f / l_s[wm + 8 + g];
        float* ob = out + ((size_t)b * NT + q0) * NH;
        #pragma unroll
        for (int ni = 0; ni < 12; ni++) {
            int col = wnv + ni * 8 + t * 2;
            int row0 = wm + g;
            int row1 = wm + 8 + g;
            *(float2*)&ob[(size_t)row0 * NH + col] =
                make_float2(o[ni][0] * inv0, o[ni][1] * inv0);
            *(float2*)&ob[(size_t)row1 * NH + col] =
                make_float2(o[ni][2] * inv1, o[ni][3] * inv1);
        }
    }
}

// ============================================================================
// Launch
// ============================================================================
extern "C" void kernel_launch(void* const* d_in, const int* in_sizes, int n_in,
                              void* d_out, int out_size)
{
    const float* x  = (const float*)d_in[0];
    const float* Wq = (const float*)d_in[1];
    const float* Wk = (const float*)d_in[2];
    const float* Wv = (const float*)d_in[3];
    float* out = (float*)d_out;

    (void)in_sizes; (void)n_in; (void)out_size;

    // QKV projections (full-N 64x192 tile, tf32 mma)
    dim3 ggrd(M_TOT / GBM, 3);      // (512, 3)
    qkv_mma<<<ggrd, 256>>>(x, Wq, Wk, Wv);

    // Attention
    size_t smem = ATTN_SMEM_FLOATS * sizeof(float);
    cudaFuncSetAttribute(attn_mma, cudaFuncAttributeMaxDynamicSharedMemorySize, (int)smem);
    dim3 agrd(NT / BQ, NB);         // (8, 64)
    attn_mma<<<agrd, 256, smem>>>(out);
}